// round 17
// baseline (speedup 1.0000x reference)
#include <cuda_runtime.h>
#include <cstdint>

// x [4,512,128] f32, y [512,128] f32 -> out [4,512,512,3] f32 (cos, L1, L2)
// L1 via SIMT packed-f32 (4x4 tile, paired-dd2 x loads); dot via bf16-split
// tensor MMA interleaved into the L1 loop. cos = dot*rx*ry, p2 = sqrt(xsq+ysq-2dot).
#define R_TOTAL 2048
#define C_TOTAL 512
#define D_DIM   128
#define NDD2    64
#define NC      32              // dd2 pairs

#define BM 128
#define BN 64
#define XC  131                 // xs2 inner dim in ull2 (128 rows + 3 pad; 131%8=3 -> STS.128 conflict-free)
#define YTS 66                  // ysT stride per dd2 (u64)
#define BTS 68                  // bf16-pair tile row stride (u32)
#define DTS 68                  // dot matrix row stride (f32), mult of 4 for float4

// smem layout (bytes)
#define XS2_OFF  0
#define YS_OFF   (XS2_OFF + NC * XC * 16)             // 67072
#define XHI_OFF  (YS_OFF + NDD2 * YTS * 8)            // 100864 (reused as dot matrix)
#define XLO_OFF  (XHI_OFF + BM * BTS * 4)             // 135680
#define YHI_OFF  (XLO_OFF + BM * BTS * 4)             // 170496
#define YLO_OFF  (YHI_OFF + BN * BTS * 4)             // 187904
#define NSQ_OFF  (YLO_OFF + BN * BTS * 4)             // 205312
#define NRN_OFF  (NSQ_OFF + 192 * 4)
#define SMEM_BYTES (NRN_OFF + 192 * 4)                // 206848

typedef unsigned long long u64;
typedef unsigned int u32;
struct __align__(16) ull2 { u64 x, y; };

__device__ __forceinline__ u64 ffma2(u64 a, u64 b, u64 c) {
    u64 d; asm("fma.rn.f32x2 %0, %1, %2, %3;" : "=l"(d) : "l"(a), "l"(b), "l"(c));
    return d;
}
__device__ __forceinline__ u64 fadd2(u64 a, u64 b) {
    u64 d; asm("add.rn.f32x2 %0, %1, %2;" : "=l"(d) : "l"(a), "l"(b));
    return d;
}
__device__ __forceinline__ float f2lo(u64 d) { return __uint_as_float((u32)(d & 0xFFFFFFFFu)); }
__device__ __forceinline__ float f2hi(u64 d) { return __uint_as_float((u32)(d >> 32)); }
__device__ __forceinline__ u64 pack2(float lo, float hi) {
    return ((u64)__float_as_uint(hi) << 32) | (u64)__float_as_uint(lo);
}
__device__ __forceinline__ u32 bfpack(float lo_elem, float hi_elem) {
    u32 r; asm("cvt.rn.bf16x2.f32 %0, %1, %2;" : "=r"(r) : "f"(hi_elem), "f"(lo_elem));
    return r;
}
__device__ __forceinline__ float bflo_f(u32 p) { return __uint_as_float(p << 16); }
__device__ __forceinline__ float bfhi_f(u32 p) { return __uint_as_float(p & 0xFFFF0000u); }

__device__ __forceinline__ void mma_bf16(float (&c)[4], const u32* a, u32 b0, u32 b1) {
    asm("mma.sync.aligned.m16n8k16.row.col.f32.bf16.bf16.f32 "
        "{%0,%1,%2,%3}, {%4,%5,%6,%7}, {%8,%9}, {%0,%1,%2,%3};"
        : "+f"(c[0]), "+f"(c[1]), "+f"(c[2]), "+f"(c[3])
        : "r"(a[0]), "r"(a[1]), "r"(a[2]), "r"(a[3]), "r"(b0), "r"(b1));
}
__device__ __forceinline__ void ldsm_x4(u32* r, u32 addr) {
    asm volatile("ldmatrix.sync.aligned.m8n8.x4.shared.b16 {%0,%1,%2,%3}, [%4];"
        : "=r"(r[0]), "=r"(r[1]), "=r"(r[2]), "=r"(r[3]) : "r"(addr));
}

__global__ void __launch_bounds__(512, 1)
dist_kernel(const float* __restrict__ x, const float* __restrict__ y,
            float* __restrict__ out) {
    extern __shared__ __align__(16) char smem[];
    ull2* xs2 = reinterpret_cast<ull2*>(smem + XS2_OFF);  // [NC][XC] f32-pair x, 2 dd2/ull2
    u64*  ysT = reinterpret_cast<u64*>(smem + YS_OFF);    // [NDD2][YTS] (-y) f32-pair
    u32* xhi = reinterpret_cast<u32*>(smem + XHI_OFF);    // [BM][BTS] bf16-pair hi
    u32* xlo = reinterpret_cast<u32*>(smem + XLO_OFF);
    u32* yhi = reinterpret_cast<u32*>(smem + YHI_OFF);    // [BN][BTS] (+y)
    u32* ylo = reinterpret_cast<u32*>(smem + YLO_OFF);
    float* nsq = reinterpret_cast<float*>(smem + NSQ_OFF);  // [192]: 128 x + 64 y
    float* nrn = reinterpret_cast<float*>(smem + NRN_OFF);
    float* dotm = reinterpret_cast<float*>(smem + XHI_OFF); // reuses xhi after loop

    const int R0 = blockIdx.x * BM;     // grid.x = 16
    const int C0 = blockIdx.y * BN;     // grid.y = 8
    const int t  = threadIdx.x;
    const int tx  = t & 15;             // y cols {4tx..4tx+3}
    const int ty4 = t >> 4;             // x rows ty4 + 32i (i<4)

    // ---- stage x: paired f32 (one STS.128 per float4) + bf16 hi/lo
    #pragma unroll
    for (int s = 0; s < 8; s++) {
        int idx = t + 512 * s;          // 0..4095
        int row = idx >> 5;             // 0..127
        int c   = idx & 31;             // dd2-pair index
        float4 v = *reinterpret_cast<const float4*>(
            x + (size_t)(R0 + row) * D_DIM + c * 4);
        ull2 wv; wv.x = pack2(v.x, v.y); wv.y = pack2(v.z, v.w);
        xs2[c * XC + row] = wv;
        u32 h0 = bfpack(v.x, v.y);
        u32 h1 = bfpack(v.z, v.w);
        u32 l0 = bfpack(v.x - bflo_f(h0), v.y - bfhi_f(h0));
        u32 l1 = bfpack(v.z - bflo_f(h1), v.w - bfhi_f(h1));
        xhi[row * BTS + 2 * c]     = h0;
        xhi[row * BTS + 2 * c + 1] = h1;
        xlo[row * BTS + 2 * c]     = l0;
        xlo[row * BTS + 2 * c + 1] = l1;
    }
    // ---- stage y: negated f32 per-dd2 + positive bf16 hi/lo
    #pragma unroll
    for (int s = 0; s < 4; s++) {
        int idx  = t + 512 * s;         // 0..2047
        int row  = idx >> 5;            // 0..63 (y row = tile col)
        int col4 = idx & 31;
        float4 v = *reinterpret_cast<const float4*>(
            y + (size_t)(C0 + row) * D_DIM + col4 * 4);
        ysT[(2 * col4) * YTS + row]     = pack2(-v.x, -v.y);
        ysT[(2 * col4 + 1) * YTS + row] = pack2(-v.z, -v.w);
        u32 h0 = bfpack(v.x, v.y);
        u32 h1 = bfpack(v.z, v.w);
        u32 l0 = bfpack(v.x - bflo_f(h0), v.y - bfhi_f(h0));
        u32 l1 = bfpack(v.z - bflo_f(h1), v.w - bfhi_f(h1));
        yhi[row * BTS + 2 * col4]     = h0;
        yhi[row * BTS + 2 * col4 + 1] = h1;
        ylo[row * BTS + 2 * col4]     = l0;
        ylo[row * BTS + 2 * col4 + 1] = l1;
    }
    __syncthreads();

    // ---- fused norms: t<128 -> x row t; 128<=t<192 -> y row t-128
    if (t < 192) {
        u64 a = 0ULL;
        if (t < 128) {
            #pragma unroll 8
            for (int c = 0; c < NC; c++) {
                ull2 v = xs2[c * XC + t];
                a = ffma2(v.x, v.x, a);
                a = ffma2(v.y, v.y, a);
            }
        } else {
            const u64* base = ysT + (t - 128);
            #pragma unroll 8
            for (int dd2 = 0; dd2 < NDD2; dd2++) {
                u64 v = base[dd2 * YTS];
                a = ffma2(v, v, a);
            }
        }
        float s = f2lo(a) + f2hi(a);
        nsq[t] = s;
        nrn[t] = rsqrtf(s);
    }
    __syncthreads();

    // ================= merged mainloop: MMA k-steps interleaved with L1 =====
    const int w    = t >> 5;
    const int lane = t & 31;
    const int gid  = lane >> 2;
    const int tig  = lane & 3;
    const int m0   = (w >> 1) * 16;
    const int nh   = (w & 1) * 32;

    const int arow = m0 + (lane & 15);
    const int acol = (lane >> 4) * 4;
    u32 xhi_sa = (u32)__cvta_generic_to_shared(xhi);
    u32 xlo_sa = (u32)__cvta_generic_to_shared(xlo);
    u32 yhi_sa = (u32)__cvta_generic_to_shared(yhi);
    u32 ylo_sa = (u32)__cvta_generic_to_shared(ylo);
    u32 aOff = (u32)(arow * BTS + acol) << 2;
    const int brow = (lane & 7) + ((lane >> 4) & 1) * 8;
    const int bcol = ((lane >> 3) & 1) * 4;
    u32 bOff0 = (u32)((nh + brow) * BTS + bcol) << 2;
    u32 bOff1 = (u32)((nh + 16 + brow) * BTS + bcol) << 2;

    float c[4][4];
    #pragma unroll
    for (int nt = 0; nt < 4; nt++)
        #pragma unroll
        for (int q = 0; q < 4; q++) c[nt][q] = 0.0f;

    const u64 ABSM = 0x7FFFFFFF7FFFFFFFULL;
    u64 acc1[4][4];
    #pragma unroll
    for (int i = 0; i < 4; i++)
        #pragma unroll
        for (int j = 0; j < 4; j++) acc1[i][j] = 0ULL;

    const ull2* pxc = xs2 + ty4;        // + c*XC + 32*i
    const u64*  pyc = ysT + 4 * tx;     // + dd2*YTS (+0 / +2)

    for (int g = 0; g < 8; g++) {
        // ---- one MMA k-step (tensor + LSU pipes) ----
        {
            u32 kb = (u32)(g * 8) << 2;
            u32 ah[4], al[4], bh0[4], bh1[4], bl0[4], bl1[4];
            ldsm_x4(ah, xhi_sa + aOff + kb);
            ldsm_x4(al, xlo_sa + aOff + kb);
            ldsm_x4(bh0, yhi_sa + bOff0 + kb);
            ldsm_x4(bh1, yhi_sa + bOff1 + kb);
            ldsm_x4(bl0, ylo_sa + bOff0 + kb);
            ldsm_x4(bl1, ylo_sa + bOff1 + kb);

            mma_bf16(c[0], ah, bh0[0], bh0[1]);
            mma_bf16(c[0], ah, bl0[0], bl0[1]);
            mma_bf16(c[0], al, bh0[0], bh0[1]);
            mma_bf16(c[1], ah, bh0[2], bh0[3]);
            mma_bf16(c[1], ah, bl0[2], bl0[3]);
            mma_bf16(c[1], al, bh0[2], bh0[3]);
            mma_bf16(c[2], ah, bh1[0], bh1[1]);
            mma_bf16(c[2], ah, bl1[0], bl1[1]);
            mma_bf16(c[2], al, bh1[0], bh1[1]);
            mma_bf16(c[3], ah, bh1[2], bh1[3]);
            mma_bf16(c[3], ah, bl1[2], bl1[3]);
            mma_bf16(c[3], al, bh1[2], bh1[3]);
        }

        // ---- 4 dd2-pairs (8 dd2) of L1 (fma pipe) ----
        #pragma unroll
        for (int cc = 0; cc < 4; cc++) {
            int cidx = 4 * g + cc;
            ull2 xv[4];
            #pragma unroll
            for (int i = 0; i < 4; i++)
                xv[i] = pxc[cidx * XC + 32 * i];        // LDS.128, 2 dd2 per row
            const u64* ye_p = pyc + (2 * cidx) * YTS;
            const u64* yo_p = ye_p + YTS;
            ull2 ya0 = *reinterpret_cast<const ull2*>(ye_p);       // dd2=2c, cols 4tx,4tx+1
            ull2 ya1 = *reinterpret_cast<const ull2*>(ye_p + 2);   // cols 4tx+2,4tx+3
            ull2 yb0 = *reinterpret_cast<const ull2*>(yo_p);       // dd2=2c+1
            ull2 yb1 = *reinterpret_cast<const ull2*>(yo_p + 2);
            u64 ye[4] = { ya0.x, ya0.y, ya1.x, ya1.y };
            u64 yo[4] = { yb0.x, yb0.y, yb1.x, yb1.y };

            #pragma unroll
            for (int i = 0; i < 4; i++) {
                #pragma unroll
                for (int j = 0; j < 4; j++) {
                    u64 d0 = fadd2(xv[i].x, ye[j]);     // dd2 = 2c
                    acc1[i][j] = fadd2(acc1[i][j], d0 & ABSM);
                    u64 d1 = fadd2(xv[i].y, yo[j]);     // dd2 = 2c+1
                    acc1[i][j] = fadd2(acc1[i][j], d1 & ABSM);
                }
            }
        }
    }

    __syncthreads();   // all warps done reading bf16 tiles

    // store dot fragments into smem (overwrites xhi region)
    #pragma unroll
    for (int nt = 0; nt < 4; nt++) {
        #pragma unroll
        for (int qh = 0; qh < 2; qh++) {
            int lr = m0 + gid + qh * 8;
            int lc = nh + nt * 8 + 2 * tig;
            *reinterpret_cast<float2*>(&dotm[lr * DTS + lc]) =
                make_float2(c[nt][qh * 2], c[nt][qh * 2 + 1]);
        }
    }
    __syncthreads();

    // ---- single coalesced epilogue: all 3 fields, 3x STG.128 per row ----
    #pragma unroll
    for (int i = 0; i < 4; i++) {
        int lrow = ty4 + 32 * i;
        int gr = R0 + lrow;
        float xsq = nsq[lrow];
        float xrn = nrn[lrow];
        float4 dv = *reinterpret_cast<const float4*>(&dotm[lrow * DTS + 4 * tx]);
        float dots[4] = { dv.x, dv.y, dv.z, dv.w };
        float o[12];
        #pragma unroll
        for (int j = 0; j < 4; j++) {
            int lcol = 4 * tx + j;
            float dot = dots[j];
            float s1 = f2lo(acc1[i][j]) + f2hi(acc1[i][j]);
            float s2 = fmaxf(xsq + nsq[128 + lcol] - 2.0f * dot, 0.0f);
            float p2 = sqrtf(s2);
            float cosv = dot * xrn * nrn[128 + lcol];
            o[3 * j + 0] = cosv;
            o[3 * j + 1] = s1;
            o[3 * j + 2] = p2;
        }
        // base = (gr*512 + C0 + 4tx)*3 floats; 48tx bytes -> 16B aligned
        size_t base = ((size_t)gr * C_TOTAL + C0 + 4 * tx) * 3;
        float4* dst = reinterpret_cast<float4*>(out + base);
        dst[0] = make_float4(o[0], o[1], o[2],  o[3]);
        dst[1] = make_float4(o[4], o[5], o[6],  o[7]);
        dst[2] = make_float4(o[8], o[9], o[10], o[11]);
    }
}

extern "C" void kernel_launch(void* const* d_in, const int* in_sizes, int n_in,
                              void* d_out, int out_size) {
    const float* x = (const float*)d_in[0];
    const float* y = (const float*)d_in[1];
    float* out = (float*)d_out;

    static int attr_done = 0;
    if (!attr_done) {
        cudaFuncSetAttribute(dist_kernel,
                             cudaFuncAttributeMaxDynamicSharedMemorySize, SMEM_BYTES);
        cudaFuncSetAttribute(dist_kernel,
                             cudaFuncAttributePreferredSharedMemoryCarveout, 100);
        attr_done = 1;
    }

    dim3 grid(R_TOTAL / BM, C_TOTAL / BN);   // 16 x 8 = 128 blocks, 1 CTA/SM, one wave
    dist_kernel<<<grid, 512, SMEM_BYTES>>>(x, y, out);
}